// round 1
// baseline (speedup 1.0000x reference)
#include <cuda_runtime.h>
#include <math.h>

#define BB 8
#define HH 32
#define DD 128
#define NLL 1
#define SS 4096
#define SPLITS 8
#define NWARP 8

// Scratch (no device allocs allowed in kernel_launch)
__device__ float g_qr[BB * HH * DD];
__device__ float g_kr[BB * HH * DD];
__device__ float g_po[BB * HH * SPLITS * DD];
__device__ float g_pm[BB * HH * SPLITS];
__device__ float g_pl[BB * HH * SPLITS];

// ---------------------------------------------------------------------------
// Kernel 1: RoPE q and k at position n-1.  grid = B*H, block = 64 (pair idx)
// ---------------------------------------------------------------------------
__global__ void rope_k(const float* __restrict__ qkv, const int* __restrict__ plen) {
    int bh = blockIdx.x;
    int b = bh / HH, h = bh % HH;
    int i = threadIdx.x;  // 0..63, handles dims 2i and 2i+1
    int n = *plen;

    float inv = powf(10000.0f, -(float)(2 * i) / (float)DD);
    float fr = (float)(n - 1) * inv;
    float sv, cv;
    sincosf(fr, &sv, &cv);

    const float* qp = qkv + ((size_t)(b * 3 + 0) * HH + h) * DD;
    const float* kp = qkv + ((size_t)(b * 3 + 1) * HH + h) * DD;
    float q0 = qp[2 * i], q1 = qp[2 * i + 1];
    float k0 = kp[2 * i], k1 = kp[2 * i + 1];

    float* qo = g_qr + (size_t)bh * DD;
    float* ko = g_kr + (size_t)bh * DD;
    // rotate_half: out[2i] = x[2i]*c - x[2i+1]*s ; out[2i+1] = x[2i+1]*c + x[2i]*s
    qo[2 * i]     = q0 * cv - q1 * sv;
    qo[2 * i + 1] = q1 * cv + q0 * sv;
    ko[2 * i]     = k0 * cv - k1 * sv;
    ko[2 * i + 1] = k1 * cv + k0 * sv;
}

// ---------------------------------------------------------------------------
// Kernel 2: split-K flash-decode partials.
// grid = (B*H, SPLITS), block = 256 (8 warps). One warp per seq position,
// 2-way unroll over positions for memory-level parallelism.
// ---------------------------------------------------------------------------
__global__ __launch_bounds__(256) void attn_partial_k(
    const float* __restrict__ qkv,
    const float* __restrict__ kc,
    const float* __restrict__ vc,
    const int* __restrict__ plen,
    const int* __restrict__ playr)
{
    __shared__ float sm_m[NWARP];
    __shared__ float sm_l[NWARP];
    __shared__ float sm_o[NWARP][DD];

    int bh = blockIdx.x;
    int split = blockIdx.y;
    int b = bh / HH, h = bh % HH;
    int n = *plen;
    int L = *playr;

    int chunk = (n + SPLITS - 1) / SPLITS;
    int s0 = split * chunk;
    int s1 = min(s0 + chunk, n);

    int warp = threadIdx.x >> 5;
    int lane = threadIdx.x & 31;

    float4 qv = ((const float4*)(g_qr + (size_t)bh * DD))[lane];
    const float scale = 0.08838834764831845f;  // 1/sqrt(128)

    const size_t sstride = (size_t)HH * DD;
    const float* kb = kc + ((size_t)(b * NLL + L) * SS) * sstride + (size_t)h * DD;
    const float* vb = vc + ((size_t)(b * NLL + L) * SS) * sstride + (size_t)h * DD;
    const float* krow_last = g_kr + (size_t)bh * DD;
    const float* vrow_last = qkv + ((size_t)(b * 3 + 2) * HH + h) * DD;

    float m = -INFINITY, l = 0.0f;
    float4 acc = make_float4(0.0f, 0.0f, 0.0f, 0.0f);

    int s = s0 + warp;
    // 2-way unrolled main loop
    for (; s + NWARP < s1; s += 2 * NWARP) {
        int sa = s, sb = s + NWARP;
        const float* kpa = (sa == n - 1) ? krow_last : kb + (size_t)sa * sstride;
        const float* kpb = (sb == n - 1) ? krow_last : kb + (size_t)sb * sstride;
        float4 kva = ((const float4*)kpa)[lane];
        float4 kvb = ((const float4*)kpb)[lane];

        float da = qv.x * kva.x + qv.y * kva.y + qv.z * kva.z + qv.w * kva.w;
        float db = qv.x * kvb.x + qv.y * kvb.y + qv.z * kvb.z + qv.w * kvb.w;
        #pragma unroll
        for (int off = 16; off; off >>= 1) {
            da += __shfl_xor_sync(0xffffffffu, da, off);
            db += __shfl_xor_sync(0xffffffffu, db, off);
        }
        da *= scale;
        db *= scale;

        const float* vpa = (sa == n - 1) ? vrow_last : vb + (size_t)sa * sstride;
        const float* vpb = (sb == n - 1) ? vrow_last : vb + (size_t)sb * sstride;
        float4 vva = ((const float4*)vpa)[lane];
        float4 vvb = ((const float4*)vpb)[lane];

        float mnew = fmaxf(m, fmaxf(da, db));
        float corr = __expf(m - mnew);
        float wa = __expf(da - mnew);
        float wb = __expf(db - mnew);
        l = l * corr + wa + wb;
        acc.x = acc.x * corr + wa * vva.x + wb * vvb.x;
        acc.y = acc.y * corr + wa * vva.y + wb * vvb.y;
        acc.z = acc.z * corr + wa * vva.z + wb * vvb.z;
        acc.w = acc.w * corr + wa * vva.w + wb * vvb.w;
        m = mnew;
    }
    // tail
    for (; s < s1; s += NWARP) {
        const float* kp = (s == n - 1) ? krow_last : kb + (size_t)s * sstride;
        float4 kv = ((const float4*)kp)[lane];
        float d = qv.x * kv.x + qv.y * kv.y + qv.z * kv.z + qv.w * kv.w;
        #pragma unroll
        for (int off = 16; off; off >>= 1)
            d += __shfl_xor_sync(0xffffffffu, d, off);
        d *= scale;

        const float* vp = (s == n - 1) ? vrow_last : vb + (size_t)s * sstride;
        float4 vv = ((const float4*)vp)[lane];

        float mnew = fmaxf(m, d);
        float corr = __expf(m - mnew);
        float w = __expf(d - mnew);
        l = l * corr + w;
        acc.x = acc.x * corr + w * vv.x;
        acc.y = acc.y * corr + w * vv.y;
        acc.z = acc.z * corr + w * vv.z;
        acc.w = acc.w * corr + w * vv.w;
        m = mnew;
    }

    // Per-warp partials to shared
    if (lane == 0) { sm_m[warp] = m; sm_l[warp] = l; }
    sm_o[warp][lane * 4 + 0] = acc.x;
    sm_o[warp][lane * 4 + 1] = acc.y;
    sm_o[warp][lane * 4 + 2] = acc.z;
    sm_o[warp][lane * 4 + 3] = acc.w;
    __syncthreads();

    // Combine 8 warps; one thread per output dim
    if (threadIdx.x < DD) {
        int d = threadIdx.x;
        float M = -INFINITY;
        #pragma unroll
        for (int w = 0; w < NWARP; w++) M = fmaxf(M, sm_m[w]);
        float Lsum = 0.0f, o = 0.0f;
        #pragma unroll
        for (int w = 0; w < NWARP; w++) {
            float mw = sm_m[w];
            float e = (mw == -INFINITY) ? 0.0f : __expf(mw - M);
            Lsum += e * sm_l[w];
            o += e * sm_o[w][d];
        }
        int idx = bh * SPLITS + split;
        g_po[(size_t)idx * DD + d] = o;
        if (d == 0) { g_pm[idx] = M; g_pl[idx] = Lsum; }
    }
}

// ---------------------------------------------------------------------------
// Kernel 3: combine SPLITS partials per (b,h).  grid = B*H, block = 128
// ---------------------------------------------------------------------------
__global__ void reduce_k(float* __restrict__ out) {
    int bh = blockIdx.x;
    int d = threadIdx.x;

    float M = -INFINITY;
    #pragma unroll
    for (int i = 0; i < SPLITS; i++) M = fmaxf(M, g_pm[bh * SPLITS + i]);

    float L = 0.0f, o = 0.0f;
    #pragma unroll
    for (int i = 0; i < SPLITS; i++) {
        float mi = g_pm[bh * SPLITS + i];
        float e = (mi == -INFINITY) ? 0.0f : __expf(mi - M);
        L += e * g_pl[bh * SPLITS + i];
        o += e * g_po[(size_t)(bh * SPLITS + i) * DD + d];
    }
    out[(size_t)bh * DD + d] = o / L;
}

// ---------------------------------------------------------------------------
extern "C" void kernel_launch(void* const* d_in, const int* in_sizes, int n_in,
                              void* d_out, int out_size) {
    const float* qkv = (const float*)d_in[0];
    const float* kc  = (const float*)d_in[1];
    const float* vc  = (const float*)d_in[2];
    const int* plen  = (const int*)d_in[3];
    const int* playr = (const int*)d_in[4];
    float* out = (float*)d_out;

    rope_k<<<BB * HH, 64>>>(qkv, plen);
    attn_partial_k<<<dim3(BB * HH, SPLITS), 256>>>(qkv, kc, vc, plen, playr);
    reduce_k<<<BB * HH, 128>>>(out);
}

// round 2
// speedup vs baseline: 1.0812x; 1.0812x over previous
#include <cuda_runtime.h>
#include <math.h>

#define BB 8
#define HH 32
#define DD 128
#define NLL 1
#define NCTA 888      // 148 SMs * 6 CTAs -> exactly one wave at occupancy 6
#define NW 8          // warps per CTA
#define MAXSLOT 8     // max CTAs contributing to one head (actual <= 5)

// Scratch (device allocs forbidden)
__device__ float g_po[BB * HH * MAXSLOT * DD];
__device__ float g_pm[BB * HH * MAXSLOT];
__device__ float g_pl[BB * HH * MAXSLOT];
__device__ int   g_cnt[BB * HH];   // zero-init; reducer resets to 0 each call

// CTA index owning flattened position p, for the balanced partition
// start(c) = c*base + min(c, rem)
__device__ __forceinline__ int cta_of(long long p, long long base, long long rem) {
    long long thr = rem * (base + 1);
    if (p < thr) return (int)(p / (base + 1));
    return (int)(rem + (p - thr) / base);
}

__global__ __launch_bounds__(256, 6) void attn_fused_k(
    const float* __restrict__ qkv,
    const float* __restrict__ kc,
    const float* __restrict__ vc,
    const int* __restrict__ plen,
    const int* __restrict__ playr,
    float* __restrict__ out,
    int Scap)                       // cache capacity along seq dim
{
    __shared__ float sq[DD];
    __shared__ float sk[DD];
    __shared__ float sm_o[NW][DD];
    __shared__ float sm_m[NW];
    __shared__ float sm_l[NW];
    __shared__ int   s_last;

    const int n = *plen;
    const int Lidx = *playr;
    const long long P = (long long)BB * HH * n;
    const long long base = P / NCTA;
    const long long rem  = P - base * NCTA;

    const int cta = blockIdx.x;
    const long long start = (long long)cta * base + min((long long)cta, rem);
    const long long cnt   = base + ((long long)cta < rem ? 1 : 0);
    const long long end   = start + cnt;
    if (cnt <= 0 || start >= P) return;

    const int bh0 = (int)(start / n);
    const int bh1 = (int)((end - 1) / n);

    const int tid  = threadIdx.x;
    const int warp = tid >> 5;
    const int lane = tid & 31;
    const float scale = rsqrtf((float)DD);
    const size_t sstride = (size_t)HH * DD;

    for (int bh = bh0; bh <= bh1; bh++) {
        const int b = bh / HH, h = bh % HH;
        const long long gs = max(start, (long long)bh * n);
        const long long ge = min(end, (long long)(bh + 1) * n);
        const int a    = (int)(gs - (long long)bh * n);
        const int bpos = (int)(ge - (long long)bh * n);

        // ---- RoPE q (threads 0..63) and k (threads 64..127) into smem ----
        if (tid < 128) {
            const int half = tid >> 6;           // 0 = q, 1 = k
            const int i = tid & 63;
            float inv = powf(10000.0f, -(float)(2 * i) / (float)DD);
            float fr = (float)(n - 1) * inv;
            float sv, cv;
            sincosf(fr, &sv, &cv);
            const float* p = qkv + ((size_t)(b * 3 + half) * HH + h) * DD;
            float x0 = p[2 * i], x1 = p[2 * i + 1];
            float* o = half ? sk : sq;
            o[2 * i]     = x0 * cv - x1 * sv;
            o[2 * i + 1] = x1 * cv + x0 * sv;
        }
        __syncthreads();

        const float4 qv = ((const float4*)sq)[lane];
        const float* kb = kc + ((size_t)(b * NLL + Lidx) * Scap) * sstride + (size_t)h * DD;
        const float* vb = vc + ((size_t)(b * NLL + Lidx) * Scap) * sstride + (size_t)h * DD;

        float m = -INFINITY, l = 0.0f;
        float4 acc = make_float4(0.0f, 0.0f, 0.0f, 0.0f);

        // last (new) position excluded from the streaming loop
        const int bmain = (bpos == n) ? n - 1 : bpos;

        int s = a + warp;
        // 2-way unrolled, all 4 loads issued before dependent math
        for (; s + NW < bmain; s += 2 * NW) {
            float4 kva = *((const float4*)(kb + (size_t)s * sstride) + lane);
            float4 kvb = *((const float4*)(kb + (size_t)(s + NW) * sstride) + lane);
            float4 vva = *((const float4*)(vb + (size_t)s * sstride) + lane);
            float4 vvb = *((const float4*)(vb + (size_t)(s + NW) * sstride) + lane);

            float da = qv.x * kva.x + qv.y * kva.y + qv.z * kva.z + qv.w * kva.w;
            float db = qv.x * kvb.x + qv.y * kvb.y + qv.z * kvb.z + qv.w * kvb.w;
            #pragma unroll
            for (int off = 16; off; off >>= 1) {
                da += __shfl_xor_sync(0xffffffffu, da, off);
                db += __shfl_xor_sync(0xffffffffu, db, off);
            }
            da *= scale;
            db *= scale;

            float mnew = fmaxf(m, fmaxf(da, db));
            float corr = __expf(m - mnew);
            float wa = __expf(da - mnew);
            float wb = __expf(db - mnew);
            l = l * corr + wa + wb;
            acc.x = acc.x * corr + wa * vva.x + wb * vvb.x;
            acc.y = acc.y * corr + wa * vva.y + wb * vvb.y;
            acc.z = acc.z * corr + wa * vva.z + wb * vvb.z;
            acc.w = acc.w * corr + wa * vva.w + wb * vvb.w;
            m = mnew;
        }
        for (; s < bmain; s += NW) {
            float4 kv = *((const float4*)(kb + (size_t)s * sstride) + lane);
            float4 vv = *((const float4*)(vb + (size_t)s * sstride) + lane);
            float d = qv.x * kv.x + qv.y * kv.y + qv.z * kv.z + qv.w * kv.w;
            #pragma unroll
            for (int off = 16; off; off >>= 1)
                d += __shfl_xor_sync(0xffffffffu, d, off);
            d *= scale;
            float mnew = fmaxf(m, d);
            float corr = __expf(m - mnew);
            float w = __expf(d - mnew);
            l = l * corr + w;
            acc.x = acc.x * corr + w * vv.x;
            acc.y = acc.y * corr + w * vv.y;
            acc.z = acc.z * corr + w * vv.z;
            acc.w = acc.w * corr + w * vv.w;
            m = mnew;
        }

        // new position (roped k from smem, v straight from qkv), warp 0 only
        if (bpos == n && warp == 0) {
            float4 kv = ((const float4*)sk)[lane];
            float d = qv.x * kv.x + qv.y * kv.y + qv.z * kv.z + qv.w * kv.w;
            #pragma unroll
            for (int off = 16; off; off >>= 1)
                d += __shfl_xor_sync(0xffffffffu, d, off);
            d *= scale;
            float4 vv = *((const float4*)(qkv + ((size_t)(b * 3 + 2) * HH + h) * DD) + lane);
            float mnew = fmaxf(m, d);
            float corr = __expf(m - mnew);
            float w = __expf(d - mnew);
            l = l * corr + w;
            acc.x = acc.x * corr + w * vv.x;
            acc.y = acc.y * corr + w * vv.y;
            acc.z = acc.z * corr + w * vv.z;
            acc.w = acc.w * corr + w * vv.w;
            m = mnew;
        }

        // ---- block combine of 8 warp partials ----
        if (lane == 0) { sm_m[warp] = m; sm_l[warp] = l; }
        ((float4*)sm_o[warp])[lane] = acc;
        __syncthreads();

        const int cta_first = cta_of((long long)bh * n, base, rem);
        const int cexp = cta_of((long long)bh * n + n - 1, base, rem) - cta_first + 1;
        const int slot = cta - cta_first;

        if (tid < DD) {
            float M = -INFINITY;
            #pragma unroll
            for (int w = 0; w < NW; w++) M = fmaxf(M, sm_m[w]);
            float Ls = 0.0f, o = 0.0f;
            #pragma unroll
            for (int w = 0; w < NW; w++) {
                float mw = sm_m[w];
                float e = (mw == -INFINITY) ? 0.0f : __expf(mw - M);
                Ls += e * sm_l[w];
                o += e * sm_o[w][tid];
            }
            g_po[((size_t)bh * MAXSLOT + slot) * DD + tid] = o;
            if (tid == 0) {
                g_pm[bh * MAXSLOT + slot] = M;
                g_pl[bh * MAXSLOT + slot] = Ls;
            }
        }
        __threadfence();
        __syncthreads();

        if (tid == 0) {
            int old = atomicAdd(&g_cnt[bh], 1);
            int last = (old == cexp - 1);
            if (last) g_cnt[bh] = 0;   // reset for next graph replay
            s_last = last;
        }
        __syncthreads();

        if (s_last) {
            __threadfence();
            if (tid < DD) {
                float M = -INFINITY;
                for (int i = 0; i < cexp; i++)
                    M = fmaxf(M, g_pm[bh * MAXSLOT + i]);
                float Ls = 0.0f, o = 0.0f;
                for (int i = 0; i < cexp; i++) {
                    float mi = g_pm[bh * MAXSLOT + i];
                    float e = (mi == -INFINITY) ? 0.0f : __expf(mi - M);
                    Ls += e * g_pl[bh * MAXSLOT + i];
                    o += e * g_po[((size_t)bh * MAXSLOT + i) * DD + tid];
                }
                out[(size_t)bh * DD + tid] = o / Ls;
            }
        }
        __syncthreads();   // protect sq/sk before next segment
    }
}

extern "C" void kernel_launch(void* const* d_in, const int* in_sizes, int n_in,
                              void* d_out, int out_size) {
    const float* qkv = (const float*)d_in[0];
    const float* kc  = (const float*)d_in[1];
    const float* vc  = (const float*)d_in[2];
    const int* plen  = (const int*)d_in[3];
    const int* playr = (const int*)d_in[4];
    float* out = (float*)d_out;

    int Scap = in_sizes[1] / (BB * NLL * HH * DD);

    attn_fused_k<<<NCTA, 256>>>(qkv, kc, vc, plen, playr, out, Scap);
}

// round 3
// speedup vs baseline: 1.0985x; 1.0160x over previous
#include <cuda_runtime.h>
#include <math.h>

#define BB 8
#define HH 32
#define DD 128
#define NLL 1
#define NCTA 592      // 148 SMs * 4 CTAs -> exactly one wave at occupancy 4
#define NW 8          // warps per CTA
#define MAXSLOT 8

// Scratch (device allocs forbidden)
__device__ float g_po[BB * HH * MAXSLOT * DD];
__device__ float g_pm[BB * HH * MAXSLOT];
__device__ float g_pl[BB * HH * MAXSLOT];
__device__ int   g_cnt[BB * HH];   // zero-init; self-resetting per replay

__device__ __forceinline__ int cta_of(long long p, long long base, long long rem) {
    long long thr = rem * (base + 1);
    if (p < thr) return (int)(p / (base + 1));
    return (int)(rem + (p - thr) / base);
}

__device__ __forceinline__ float4 ldcs4(const float4* p) {
    return __ldcs(p);
}

__global__ __launch_bounds__(256, 4) void attn_fused_k(
    const float* __restrict__ qkv,
    const float* __restrict__ kc,
    const float* __restrict__ vc,
    const int* __restrict__ plen,
    const int* __restrict__ playr,
    float* __restrict__ out,
    int Scap)
{
    __shared__ float sq[DD];
    __shared__ float sk[DD];
    __shared__ float sm_o[NW][DD];
    __shared__ float sm_m[NW];
    __shared__ float sm_l[NW];
    __shared__ int   s_last;

    const int n = *plen;
    const int Lidx = *playr;
    const long long P = (long long)BB * HH * n;
    const long long base = P / NCTA;
    const long long rem  = P - base * NCTA;

    const int cta = blockIdx.x;
    const long long start = (long long)cta * base + min((long long)cta, rem);
    const long long cnt   = base + ((long long)cta < rem ? 1 : 0);
    const long long end   = start + cnt;
    if (cnt <= 0 || start >= P) return;

    const int bh0 = (int)(start / n);
    const int bh1 = (int)((end - 1) / n);

    const int tid  = threadIdx.x;
    const int warp = tid >> 5;
    const int lane = tid & 31;
    const float scale = rsqrtf((float)DD);
    const size_t sstride = (size_t)HH * DD;          // floats between seq positions
    const size_t wstep   = (size_t)NW * sstride;     // one warp-stride

    for (int bh = bh0; bh <= bh1; bh++) {
        const int b = bh / HH, h = bh % HH;
        const long long gs = max(start, (long long)bh * n);
        const long long ge = min(end, (long long)(bh + 1) * n);
        const int a    = (int)(gs - (long long)bh * n);
        const int bpos = (int)(ge - (long long)bh * n);

        // ---- RoPE q (threads 0..63) and k (threads 64..127) into smem ----
        if (tid < 128) {
            const int half = tid >> 6;
            const int i = tid & 63;
            float inv = powf(10000.0f, -(float)(2 * i) / (float)DD);
            float fr = (float)(n - 1) * inv;
            float sv, cv;
            sincosf(fr, &sv, &cv);
            const float* p = qkv + ((size_t)(b * 3 + half) * HH + h) * DD;
            float x0 = p[2 * i], x1 = p[2 * i + 1];
            float* o = half ? sk : sq;
            o[2 * i]     = x0 * cv - x1 * sv;
            o[2 * i + 1] = x1 * cv + x0 * sv;
        }
        __syncthreads();

        const float4 qv = ((const float4*)sq)[lane];
        const float* kbase = kc + ((size_t)(b * NLL + Lidx) * Scap) * sstride + (size_t)h * DD;
        const float* vbase = vc + ((size_t)(b * NLL + Lidx) * Scap) * sstride + (size_t)h * DD;

        float m = -INFINITY, l = 0.0f;
        float4 acc = make_float4(0.0f, 0.0f, 0.0f, 0.0f);

        const int bmain = (bpos == n) ? n - 1 : bpos;

        int s = a + warp;
        const float4* kp = (const float4*)(kbase + (size_t)s * sstride) + lane;
        const float4* vp = (const float4*)(vbase + (size_t)s * sstride) + lane;
        const size_t wstep4 = wstep / 4;   // float4 units

        // ---- 4-way unrolled main loop: 8 loads front-batched ----
        for (; s + 3 * NW < bmain; s += 4 * NW) {
            float4 k0 = ldcs4(kp);
            float4 k1 = ldcs4(kp + wstep4);
            float4 k2 = ldcs4(kp + 2 * wstep4);
            float4 k3 = ldcs4(kp + 3 * wstep4);
            float4 v0 = ldcs4(vp);
            float4 v1 = ldcs4(vp + wstep4);
            float4 v2 = ldcs4(vp + 2 * wstep4);
            float4 v3 = ldcs4(vp + 3 * wstep4);
            kp += 4 * wstep4;
            vp += 4 * wstep4;

            float d0 = qv.x * k0.x + qv.y * k0.y + qv.z * k0.z + qv.w * k0.w;
            float d1 = qv.x * k1.x + qv.y * k1.y + qv.z * k1.z + qv.w * k1.w;
            float d2 = qv.x * k2.x + qv.y * k2.y + qv.z * k2.z + qv.w * k2.w;
            float d3 = qv.x * k3.x + qv.y * k3.y + qv.z * k3.z + qv.w * k3.w;
            #pragma unroll
            for (int off = 16; off; off >>= 1) {
                d0 += __shfl_xor_sync(0xffffffffu, d0, off);
                d1 += __shfl_xor_sync(0xffffffffu, d1, off);
                d2 += __shfl_xor_sync(0xffffffffu, d2, off);
                d3 += __shfl_xor_sync(0xffffffffu, d3, off);
            }
            d0 *= scale; d1 *= scale; d2 *= scale; d3 *= scale;

            float mnew = fmaxf(fmaxf(fmaxf(m, d0), fmaxf(d1, d2)), d3);
            float corr = __expf(m - mnew);
            float w0 = __expf(d0 - mnew);
            float w1 = __expf(d1 - mnew);
            float w2 = __expf(d2 - mnew);
            float w3 = __expf(d3 - mnew);
            l = l * corr + (w0 + w1) + (w2 + w3);
            acc.x = acc.x * corr + w0 * v0.x + w1 * v1.x + w2 * v2.x + w3 * v3.x;
            acc.y = acc.y * corr + w0 * v0.y + w1 * v1.y + w2 * v2.y + w3 * v3.y;
            acc.z = acc.z * corr + w0 * v0.z + w1 * v1.z + w2 * v2.z + w3 * v3.z;
            acc.w = acc.w * corr + w0 * v0.w + w1 * v1.w + w2 * v2.w + w3 * v3.w;
            m = mnew;
        }
        // ---- tail ----
        for (; s < bmain; s += NW) {
            float4 kv = ldcs4(kp);
            float4 vv = ldcs4(vp);
            kp += wstep4;
            vp += wstep4;
            float d = qv.x * kv.x + qv.y * kv.y + qv.z * kv.z + qv.w * kv.w;
            #pragma unroll
            for (int off = 16; off; off >>= 1)
                d += __shfl_xor_sync(0xffffffffu, d, off);
            d *= scale;
            float mnew = fmaxf(m, d);
            float corr = __expf(m - mnew);
            float w = __expf(d - mnew);
            l = l * corr + w;
            acc.x = acc.x * corr + w * vv.x;
            acc.y = acc.y * corr + w * vv.y;
            acc.z = acc.z * corr + w * vv.z;
            acc.w = acc.w * corr + w * vv.w;
            m = mnew;
        }

        // ---- new position (roped k from smem, v from qkv), warp 0 only ----
        if (bpos == n && warp == 0) {
            float4 kv = ((const float4*)sk)[lane];
            float d = qv.x * kv.x + qv.y * kv.y + qv.z * kv.z + qv.w * kv.w;
            #pragma unroll
            for (int off = 16; off; off >>= 1)
                d += __shfl_xor_sync(0xffffffffu, d, off);
            d *= scale;
            float4 vv = *((const float4*)(qkv + ((size_t)(b * 3 + 2) * HH + h) * DD) + lane);
            float mnew = fmaxf(m, d);
            float corr = __expf(m - mnew);
            float w = __expf(d - mnew);
            l = l * corr + w;
            acc.x = acc.x * corr + w * vv.x;
            acc.y = acc.y * corr + w * vv.y;
            acc.z = acc.z * corr + w * vv.z;
            acc.w = acc.w * corr + w * vv.w;
            m = mnew;
        }

        // ---- block combine of 8 warp partials ----
        if (lane == 0) { sm_m[warp] = m; sm_l[warp] = l; }
        ((float4*)sm_o[warp])[lane] = acc;
        __syncthreads();

        const int cta_first = cta_of((long long)bh * n, base, rem);
        const int cexp = cta_of((long long)bh * n + n - 1, base, rem) - cta_first + 1;
        const int slot = cta - cta_first;

        if (tid < DD) {
            float M = -INFINITY;
            #pragma unroll
            for (int w = 0; w < NW; w++) M = fmaxf(M, sm_m[w]);
            float Ls = 0.0f, o = 0.0f;
            #pragma unroll
            for (int w = 0; w < NW; w++) {
                float mw = sm_m[w];
                float e = (mw == -INFINITY) ? 0.0f : __expf(mw - M);
                Ls += e * sm_l[w];
                o += e * sm_o[w][tid];
            }
            g_po[((size_t)bh * MAXSLOT + slot) * DD + tid] = o;
            if (tid == 0) {
                g_pm[bh * MAXSLOT + slot] = M;
                g_pl[bh * MAXSLOT + slot] = Ls;
            }
        }
        __threadfence();
        __syncthreads();

        if (tid == 0) {
            int old = atomicAdd(&g_cnt[bh], 1);
            int last = (old == cexp - 1);
            if (last) g_cnt[bh] = 0;
            s_last = last;
        }
        __syncthreads();

        if (s_last) {
            __threadfence();
            if (tid < DD) {
                float M = -INFINITY;
                for (int i = 0; i < cexp; i++)
                    M = fmaxf(M, g_pm[bh * MAXSLOT + i]);
                float Ls = 0.0f, o = 0.0f;
                for (int i = 0; i < cexp; i++) {
                    float mi = g_pm[bh * MAXSLOT + i];
                    float e = (mi == -INFINITY) ? 0.0f : __expf(mi - M);
                    Ls += e * g_pl[bh * MAXSLOT + i];
                    o += e * g_po[((size_t)bh * MAXSLOT + i) * DD + tid];
                }
                out[(size_t)bh * DD + tid] = o / Ls;
            }
        }
        __syncthreads();
    }
}

extern "C" void kernel_launch(void* const* d_in, const int* in_sizes, int n_in,
                              void* d_out, int out_size) {
    const float* qkv = (const float*)d_in[0];
    const float* kc  = (const float*)d_in[1];
    const float* vc  = (const float*)d_in[2];
    const int* plen  = (const int*)d_in[3];
    const int* playr = (const int*)d_in[4];
    float* out = (float*)d_out;

    int Scap = in_sizes[1] / (BB * NLL * HH * DD);

    attn_fused_k<<<NCTA, 256>>>(qkv, kc, vc, plen, playr, out, Scap);
}

// round 4
// speedup vs baseline: 1.1092x; 1.0097x over previous
#include <cuda_runtime.h>
#include <math.h>

#define BB 8
#define HH 32
#define DD 128
#define NLL 1
#define NCTA 740      // 148 SMs * 5 CTAs -> exactly one wave at occupancy 5
#define NW 8          // warps per CTA
#define MAXSLOT 8

// Scratch (device allocs forbidden)
__device__ float g_po[BB * HH * MAXSLOT * DD];
__device__ float g_pm[BB * HH * MAXSLOT];
__device__ float g_pl[BB * HH * MAXSLOT];
__device__ int   g_cnt[BB * HH];   // zero-init; self-resetting per replay

__device__ __forceinline__ int cta_of(long long p, long long base, long long rem) {
    long long thr = rem * (base + 1);
    if (p < thr) return (int)(p / (base + 1));
    return (int)(rem + (p - thr) / base);
}

__device__ __forceinline__ float4 ldcs4(const float4* p) {
    return __ldcs(p);
}

__global__ __launch_bounds__(256, 5) void attn_fused_k(
    const float* __restrict__ qkv,
    const float* __restrict__ kc,
    const float* __restrict__ vc,
    const int* __restrict__ plen,
    const int* __restrict__ playr,
    float* __restrict__ out,
    int Scap)
{
    __shared__ float sq[DD];
    __shared__ float sk[DD];
    __shared__ float sm_o[NW][DD];
    __shared__ float sm_m[NW];
    __shared__ float sm_l[NW];
    __shared__ int   s_last;

    const int n = *plen;
    const int Lidx = *playr;
    const long long P = (long long)BB * HH * n;
    const long long base = P / NCTA;
    const long long rem  = P - base * NCTA;

    const int cta = blockIdx.x;
    const long long start = (long long)cta * base + min((long long)cta, rem);
    const long long cnt   = base + ((long long)cta < rem ? 1 : 0);
    const long long end   = start + cnt;
    if (cnt <= 0 || start >= P) return;

    const int bh0 = (int)(start / n);
    const int bh1 = (int)((end - 1) / n);

    const int tid  = threadIdx.x;
    const int warp = tid >> 5;
    const int lane = tid & 31;
    const float scale = rsqrtf((float)DD);
    const size_t sstride = (size_t)HH * DD;          // floats between seq positions
    const size_t wstep   = (size_t)NW * sstride;     // one warp-stride

    for (int bh = bh0; bh <= bh1; bh++) {
        const int b = bh / HH, h = bh % HH;
        const long long gs = max(start, (long long)bh * n);
        const long long ge = min(end, (long long)(bh + 1) * n);
        const int a    = (int)(gs - (long long)bh * n);
        const int bpos = (int)(ge - (long long)bh * n);

        // ---- RoPE q (threads 0..63) and k (threads 64..127) into smem ----
        if (tid < 128) {
            const int half = tid >> 6;
            const int i = tid & 63;
            float inv = powf(10000.0f, -(float)(2 * i) / (float)DD);
            float fr = (float)(n - 1) * inv;
            float sv, cv;
            sincosf(fr, &sv, &cv);
            const float* p = qkv + ((size_t)(b * 3 + half) * HH + h) * DD;
            float x0 = p[2 * i], x1 = p[2 * i + 1];
            float* o = half ? sk : sq;
            o[2 * i]     = x0 * cv - x1 * sv;
            o[2 * i + 1] = x1 * cv + x0 * sv;
        }
        __syncthreads();

        const float4 qv = ((const float4*)sq)[lane];
        const float* kbase = kc + ((size_t)(b * NLL + Lidx) * Scap) * sstride + (size_t)h * DD;
        const float* vbase = vc + ((size_t)(b * NLL + Lidx) * Scap) * sstride + (size_t)h * DD;

        float m = -INFINITY, l = 0.0f;
        float4 acc = make_float4(0.0f, 0.0f, 0.0f, 0.0f);

        const int bmain = (bpos == n) ? n - 1 : bpos;

        int s = a + warp;
        const float4* kp = (const float4*)(kbase + (size_t)s * sstride) + lane;
        const float4* vp = (const float4*)(vbase + (size_t)s * sstride) + lane;
        const size_t wstep4 = wstep / 4;   // float4 units

        // ---- 4-way unrolled main loop: 8 loads front-batched ----
        for (; s + 3 * NW < bmain; s += 4 * NW) {
            float4 k0 = ldcs4(kp);
            float4 k1 = ldcs4(kp + wstep4);
            float4 k2 = ldcs4(kp + 2 * wstep4);
            float4 k3 = ldcs4(kp + 3 * wstep4);
            float4 v0 = ldcs4(vp);
            float4 v1 = ldcs4(vp + wstep4);
            float4 v2 = ldcs4(vp + 2 * wstep4);
            float4 v3 = ldcs4(vp + 3 * wstep4);
            kp += 4 * wstep4;
            vp += 4 * wstep4;

            float d0 = qv.x * k0.x + qv.y * k0.y + qv.z * k0.z + qv.w * k0.w;
            float d1 = qv.x * k1.x + qv.y * k1.y + qv.z * k1.z + qv.w * k1.w;
            float d2 = qv.x * k2.x + qv.y * k2.y + qv.z * k2.z + qv.w * k2.w;
            float d3 = qv.x * k3.x + qv.y * k3.y + qv.z * k3.z + qv.w * k3.w;
            #pragma unroll
            for (int off = 16; off; off >>= 1) {
                d0 += __shfl_xor_sync(0xffffffffu, d0, off);
                d1 += __shfl_xor_sync(0xffffffffu, d1, off);
                d2 += __shfl_xor_sync(0xffffffffu, d2, off);
                d3 += __shfl_xor_sync(0xffffffffu, d3, off);
            }
            d0 *= scale; d1 *= scale; d2 *= scale; d3 *= scale;

            float mnew = fmaxf(fmaxf(fmaxf(m, d0), fmaxf(d1, d2)), d3);
            float corr = __expf(m - mnew);
            float w0 = __expf(d0 - mnew);
            float w1 = __expf(d1 - mnew);
            float w2 = __expf(d2 - mnew);
            float w3 = __expf(d3 - mnew);
            l = l * corr + (w0 + w1) + (w2 + w3);
            acc.x = acc.x * corr + w0 * v0.x + w1 * v1.x + w2 * v2.x + w3 * v3.x;
            acc.y = acc.y * corr + w0 * v0.y + w1 * v1.y + w2 * v2.y + w3 * v3.y;
            acc.z = acc.z * corr + w0 * v0.z + w1 * v1.z + w2 * v2.z + w3 * v3.z;
            acc.w = acc.w * corr + w0 * v0.w + w1 * v1.w + w2 * v2.w + w3 * v3.w;
            m = mnew;
        }
        // ---- tail ----
        for (; s < bmain; s += NW) {
            float4 kv = ldcs4(kp);
            float4 vv = ldcs4(vp);
            kp += wstep4;
            vp += wstep4;
            float d = qv.x * kv.x + qv.y * kv.y + qv.z * kv.z + qv.w * kv.w;
            #pragma unroll
            for (int off = 16; off; off >>= 1)
                d += __shfl_xor_sync(0xffffffffu, d, off);
            d *= scale;
            float mnew = fmaxf(m, d);
            float corr = __expf(m - mnew);
            float w = __expf(d - mnew);
            l = l * corr + w;
            acc.x = acc.x * corr + w * vv.x;
            acc.y = acc.y * corr + w * vv.y;
            acc.z = acc.z * corr + w * vv.z;
            acc.w = acc.w * corr + w * vv.w;
            m = mnew;
        }

        // ---- new position (roped k from smem, v from qkv), warp 0 only ----
        if (bpos == n && warp == 0) {
            float4 kv = ((const float4*)sk)[lane];
            float d = qv.x * kv.x + qv.y * kv.y + qv.z * kv.z + qv.w * kv.w;
            #pragma unroll
            for (int off = 16; off; off >>= 1)
                d += __shfl_xor_sync(0xffffffffu, d, off);
            d *= scale;
            float4 vv = *((const float4*)(qkv + ((size_t)(b * 3 + 2) * HH + h) * DD) + lane);
            float mnew = fmaxf(m, d);
            float corr = __expf(m - mnew);
            float w = __expf(d - mnew);
            l = l * corr + w;
            acc.x = acc.x * corr + w * vv.x;
            acc.y = acc.y * corr + w * vv.y;
            acc.z = acc.z * corr + w * vv.z;
            acc.w = acc.w * corr + w * vv.w;
            m = mnew;
        }

        // ---- block combine of 8 warp partials ----
        if (lane == 0) { sm_m[warp] = m; sm_l[warp] = l; }
        ((float4*)sm_o[warp])[lane] = acc;
        __syncthreads();

        const int cta_first = cta_of((long long)bh * n, base, rem);
        const int cexp = cta_of((long long)bh * n + n - 1, base, rem) - cta_first + 1;
        const int slot = cta - cta_first;

        if (tid < DD) {
            float M = -INFINITY;
            #pragma unroll
            for (int w = 0; w < NW; w++) M = fmaxf(M, sm_m[w]);
            float Ls = 0.0f, o = 0.0f;
            #pragma unroll
            for (int w = 0; w < NW; w++) {
                float mw = sm_m[w];
                float e = (mw == -INFINITY) ? 0.0f : __expf(mw - M);
                Ls += e * sm_l[w];
                o += e * sm_o[w][tid];
            }
            g_po[((size_t)bh * MAXSLOT + slot) * DD + tid] = o;
            if (tid == 0) {
                g_pm[bh * MAXSLOT + slot] = M;
                g_pl[bh * MAXSLOT + slot] = Ls;
            }
        }
        __threadfence();
        __syncthreads();

        if (tid == 0) {
            int old = atomicAdd(&g_cnt[bh], 1);
            int last = (old == cexp - 1);
            if (last) g_cnt[bh] = 0;
            s_last = last;
        }
        __syncthreads();

        if (s_last) {
            __threadfence();
            if (tid < DD) {
                float M = -INFINITY;
                for (int i = 0; i < cexp; i++)
                    M = fmaxf(M, g_pm[bh * MAXSLOT + i]);
                float Ls = 0.0f, o = 0.0f;
                for (int i = 0; i < cexp; i++) {
                    float mi = g_pm[bh * MAXSLOT + i];
                    float e = (mi == -INFINITY) ? 0.0f : __expf(mi - M);
                    Ls += e * g_pl[bh * MAXSLOT + i];
                    o += e * g_po[((size_t)bh * MAXSLOT + i) * DD + tid];
                }
                out[(size_t)bh * DD + tid] = o / Ls;
            }
        }
        __syncthreads();
    }
}

extern "C" void kernel_launch(void* const* d_in, const int* in_sizes, int n_in,
                              void* d_out, int out_size) {
    const float* qkv = (const float*)d_in[0];
    const float* kc  = (const float*)d_in[1];
    const float* vc  = (const float*)d_in[2];
    const int* plen  = (const int*)d_in[3];
    const int* playr = (const int*)d_in[4];
    float* out = (float*)d_out;

    int Scap = in_sizes[1] / (BB * NLL * HH * DD);

    attn_fused_k<<<NCTA, 256>>>(qkv, kc, vc, plen, playr, out, Scap);
}